// round 10
// baseline (speedup 1.0000x reference)
#include <cuda_runtime.h>

#define NATOMS  1024
#define NBATCH  32
#define NTILE   8
#define TILE    128
#define HPAIRS  32            // packed j-pairs per half-tile (64 atoms)
#define NPB     36            // tile-pairs per batch: 8 diag + 28 off-diag
#define BPB     (2 * NPB)     // blocks per batch (x2 j-halves) = 72
#define THREADS 64            // each thread owns TWO i-atoms (tid, tid+64)
// grid = NBATCH * BPB = 2304 blocks of 64 threads

typedef unsigned long long ull;

__device__ __forceinline__ ull f2pack(float lo, float hi) {
    ull r;
    asm("mov.b64 %0, {%1, %2};" : "=l"(r)
        : "r"(__float_as_uint(lo)), "r"(__float_as_uint(hi)));
    return r;
}
__device__ __forceinline__ void f2unpack(ull v, float& lo, float& hi) {
    unsigned a, b;
    asm("mov.b64 {%0, %1}, %2;" : "=r"(a), "=r"(b) : "l"(v));
    lo = __uint_as_float(a);
    hi = __uint_as_float(b);
}
__device__ __forceinline__ ull f2add(ull a, ull b) {
    ull r; asm("add.rn.f32x2 %0, %1, %2;" : "=l"(r) : "l"(a), "l"(b)); return r;
}
__device__ __forceinline__ ull f2mul(ull a, ull b) {
    ull r; asm("mul.rn.f32x2 %0, %1, %2;" : "=l"(r) : "l"(a), "l"(b)); return r;
}
__device__ __forceinline__ ull f2fma(ull a, ull b, ull c) {
    ull r; asm("fma.rn.f32x2 %0, %1, %2, %3;" : "=l"(r) : "l"(a), "l"(b), "l"(c)); return r;
}

// Pre-pass (one block per batch): compute mean; init forces with oscillator force
// and out[b] with oscillator energy. Covers every output element exactly once.
__global__ __launch_bounds__(256) void lj_pre(const float* __restrict__ pos,
                                              float* __restrict__ out) {
    __shared__ float sx[NATOMS], sy[NATOMS], sz[NATOMS];
    __shared__ float wr[8 * 3];
    __shared__ float er[8];
    __shared__ float smean[3];

    const int b = blockIdx.x, tid = threadIdx.x;
    const int lane = tid & 31, warp = tid >> 5;
    const float* __restrict__ p = pos + (size_t)b * NATOMS * 3;

    float mx = 0.0f, my = 0.0f, mz = 0.0f;
    for (int a = tid; a < NATOMS; a += 256) {
        float x = p[3 * a + 0], y = p[3 * a + 1], z = p[3 * a + 2];
        sx[a] = x; sy[a] = y; sz[a] = z;
        mx += x; my += y; mz += z;
    }
    #pragma unroll
    for (int o = 16; o > 0; o >>= 1) {
        mx += __shfl_xor_sync(0xFFFFFFFFu, mx, o);
        my += __shfl_xor_sync(0xFFFFFFFFu, my, o);
        mz += __shfl_xor_sync(0xFFFFFFFFu, mz, o);
    }
    if (lane == 0) { wr[warp * 3] = mx; wr[warp * 3 + 1] = my; wr[warp * 3 + 2] = mz; }
    __syncthreads();
    if (tid == 0) {
        float ax = 0.0f, ay = 0.0f, az = 0.0f;
        #pragma unroll
        for (int k = 0; k < 8; k++) { ax += wr[k*3]; ay += wr[k*3+1]; az += wr[k*3+2]; }
        const float inv_n = 1.0f / (float)NATOMS;
        smean[0] = ax * inv_n; smean[1] = ay * inv_n; smean[2] = az * inv_n;
    }
    __syncthreads();
    const float cmx = smean[0], cmy = smean[1], cmz = smean[2];

    float e = 0.0f;
    float* __restrict__ f = out + NBATCH + (size_t)b * NATOMS * 3;
    for (int a = tid; a < NATOMS; a += 256) {
        float xc = sx[a] - cmx, yc = sy[a] - cmy, zc = sz[a] - cmz;
        f[3 * a + 0] = -0.25f * xc;
        f[3 * a + 1] = -0.25f * yc;
        f[3 * a + 2] = -0.25f * zc;
        e += fmaf(xc, xc, fmaf(yc, yc, zc * zc));
    }
    e *= 0.125f;
    #pragma unroll
    for (int o = 16; o > 0; o >>= 1) e += __shfl_xor_sync(0xFFFFFFFFu, e, o);
    if (lane == 0) er[warp] = e;
    __syncthreads();
    if (tid == 0) {
        float es = 0.0f;
        #pragma unroll
        for (int k = 0; k < 8; k++) es += er[k];
        out[b] = es;
    }
}

// LJ core for one packed i vs one packed j-pair. Returns c2; accumulates e/f.
__device__ __forceinline__ ull lj_core(
    ull xi2, ull yi2, ull zi2, ull nx2, ull ny2, ull nz2,
    int m, int m0, int m1, bool self_mask, ull MINUS1,
    ull& dx2o, ull& dy2o, ull& dz2o,
    ull& fx2, ull& fy2, ull& fz2, ull& ae)
{
    ull dx2 = f2add(xi2, nx2);
    ull dy2 = f2add(yi2, ny2);
    ull dz2 = f2add(zi2, nz2);
    ull sq2 = f2mul(dx2, dx2);
    sq2 = f2fma(dy2, dy2, sq2);
    sq2 = f2fma(dz2, dz2, sq2);
    float s0, s1;
    f2unpack(sq2, s0, s1);
    if (self_mask) {                    // self-pair -> rcp underflows to 0
        s0 = (m == m0) ? 3.0e38f : s0;
        s1 = (m == m1) ? 3.0e38f : s1;
    }
    float r0 = __fdividef(1.0f, s0);    // MUFU.RCP
    float r1 = __fdividef(1.0f, s1);
    ull invsq2 = f2pack(r0, r1);
    ull t4    = f2mul(invsq2, invsq2);
    ull inv6  = f2mul(t4, invsq2);
    ull inv12 = f2mul(inv6, inv6);
    ull diff  = f2fma(inv6, MINUS1, inv12);     // inv12 - inv6
    ae = f2add(ae, f2fma(inv6, MINUS1, diff));  // += inv12 - 2*inv6
    ull c2 = f2mul(diff, invsq2);
    fx2 = f2fma(c2, dx2, fx2);
    fy2 = f2fma(c2, dy2, fy2);
    fz2 = f2fma(c2, dz2, fz2);
    dx2o = dx2; dy2o = dy2; dz2o = dz2;
    return c2;
}

__global__ __launch_bounds__(THREADS, 12) void lj_kernel(const float* __restrict__ pos,
                                                         float* __restrict__ out) {
    __shared__ ulonglong2 sxy[HPAIRS];     // packed negated j-half (-x0,-x1),(-y0,-y1)
    __shared__ ull        szz[HPAIRS];     // (-z0,-z1)
    __shared__ ull        fjx[2 * HPAIRS]; // per-warp j-force accumulators (packed)
    __shared__ ull        fjy[2 * HPAIRS];
    __shared__ ull        fjz[2 * HPAIRS];
    __shared__ float      ered[2];

    const int bi  = blockIdx.x;
    const int b   = bi / BPB;
    int rem = bi - b * BPB;
    const int h   = rem & 1;               // j-half: 0 -> j[0:64), 1 -> j[64:128)
    rem >>= 1;                             // tile-pair rank 0..35
    int ta = 0;
    while (rem >= NTILE - ta) { rem -= NTILE - ta; ta++; }
    const int tb = ta + rem;               // ta <= tb
    const bool diag = (ta == tb);

    const int tid  = threadIdx.x;
    const int lane = tid & 31;
    const int warp = tid >> 5;

    const float* __restrict__ p = pos + (size_t)b * NATOMS * 3;

    // two owned i-atoms
    const int i0 = ta * TILE + tid;
    const int i1 = i0 + THREADS;
    const float xa = p[3 * i0 + 0], ya = p[3 * i0 + 1], za = p[3 * i0 + 2];
    const float xb = p[3 * i1 + 0], yb = p[3 * i1 + 1], zb = p[3 * i1 + 2];

    // stage packed, negated j-half: pair m -> atoms (2m, 2m+1) of this 64-atom half
    if (tid < HPAIRS) {
        const int j0 = tb * TILE + h * 64 + 2 * tid;
        float x0 = p[3 * j0 + 0], y0 = p[3 * j0 + 1], z0 = p[3 * j0 + 2];
        float x1 = p[3 * j0 + 3], y1 = p[3 * j0 + 4], z1 = p[3 * j0 + 5];
        ulonglong2 v;
        v.x = f2pack(-x0, -x1);
        v.y = f2pack(-y0, -y1);
        sxy[tid] = v;
        szz[tid] = f2pack(-z0, -z1);
    }
    // zero per-warp j-force accumulators (2 warps x 32 pairs)
    fjx[tid] = 0; fjy[tid] = 0; fjz[tid] = 0;   // tid covers 2*HPAIRS = 64
    __syncthreads();

    const ull xa2 = f2pack(xa, xa), ya2 = f2pack(ya, ya), za2 = f2pack(za, za);
    const ull xb2 = f2pack(xb, xb), yb2 = f2pack(yb, yb), zb2 = f2pack(zb, zb);
    const ull MINUS1 = f2pack(-1.0f, -1.0f);

    ull fxa = 0, fya = 0, fza = 0, aea = 0;
    ull fxb = 0, fyb = 0, fzb = 0, aeb = 0;

    if (diag) {
        // self-tile: full directed loop; each ordered pair computed from i side.
        // i0 (=tid) lives in j-half 0; i1 (=tid+64) lives in j-half 1.
        const int slot = tid & 1;
        const int ms   = tid >> 1;
        const int m0a = (h == 0 && slot == 0) ? ms : -1;
        const int m1a = (h == 0 && slot == 1) ? ms : -1;
        const int m0b = (h == 1 && slot == 0) ? ms : -1;
        const int m1b = (h == 1 && slot == 1) ? ms : -1;
        ull d0, d1, d2;
        #pragma unroll 2
        for (int m = 0; m < HPAIRS; m++) {
            ulonglong2 q = sxy[m];
            ull nz2 = szz[m];
            lj_core(xa2, ya2, za2, q.x, q.y, nz2, m, m0a, m1a, true, MINUS1,
                    d0, d1, d2, fxa, fya, fza, aea);
            lj_core(xb2, yb2, zb2, q.x, q.y, nz2, m, m0b, m1b, true, MINUS1,
                    d0, d1, d2, fxb, fyb, fzb, aeb);
        }
    } else {
        // cross-tile: each pair once; per-warp shared j-accumulators, one RMW per iter
        volatile ull* vfx = fjx + warp * HPAIRS;
        volatile ull* vfy = fjy + warp * HPAIRS;
        volatile ull* vfz = fjz + warp * HPAIRS;
        ull dxa, dya, dza, dxb, dyb, dzb;
        #pragma unroll 2
        for (int m = 0; m < HPAIRS; m++) {
            const int pp = (m + lane) & (HPAIRS - 1);   // lanes on distinct pairs
            ulonglong2 q = sxy[pp];
            ull nz2 = szz[pp];
            ull ca = lj_core(xa2, ya2, za2, q.x, q.y, nz2, 0, -1, -1, false, MINUS1,
                             dxa, dya, dza, fxa, fya, fza, aea);
            ull cb = lj_core(xb2, yb2, zb2, q.x, q.y, nz2, 0, -1, -1, false, MINUS1,
                             dxb, dyb, dzb, fxb, fyb, fzb, aeb);
            vfx[pp] = f2fma(cb, dxb, f2fma(ca, dxa, vfx[pp]));
            vfy[pp] = f2fma(cb, dyb, f2fma(ca, dya, vfy[pp]));
            vfz[pp] = f2fma(cb, dzb, f2fma(ca, dza, vfz[pp]));
        }
    }

    const float ew = diag ? 0.5f : 1.0f;
    float e;
    {
        float l0, h0, l1, h1;
        f2unpack(aea, l0, h0);
        f2unpack(aeb, l1, h1);
        e = ew * (l0 + h0 + l1 + h1);
    }

    // i-side forces (output preloaded with oscillator force by lj_pre)
    {
        float lo, hi;
        float* __restrict__ fA = out + NBATCH + (size_t)(b * NATOMS + i0) * 3;
        f2unpack(fxa, lo, hi); atomicAdd(fA + 0, 12.0f * (lo + hi));
        f2unpack(fya, lo, hi); atomicAdd(fA + 1, 12.0f * (lo + hi));
        f2unpack(fza, lo, hi); atomicAdd(fA + 2, 12.0f * (lo + hi));
        float* __restrict__ fB = out + NBATCH + (size_t)(b * NATOMS + i1) * 3;
        f2unpack(fxb, lo, hi); atomicAdd(fB + 0, 12.0f * (lo + hi));
        f2unpack(fyb, lo, hi); atomicAdd(fB + 1, 12.0f * (lo + hi));
        f2unpack(fzb, lo, hi); atomicAdd(fB + 2, 12.0f * (lo + hi));
    }

    __syncthreads();

    // j-side forces (off-diag only): reduce the 2 warp copies, negate, scale
    if (!diag && tid < HPAIRS) {
        ull sx = f2add(fjx[tid], fjx[HPAIRS + tid]);
        ull sy = f2add(fjy[tid], fjy[HPAIRS + tid]);
        ull sz = f2add(fjz[tid], fjz[HPAIRS + tid]);
        float sx0, sx1, sy0, sy1, sz0, sz1;
        f2unpack(sx, sx0, sx1);
        f2unpack(sy, sy0, sy1);
        f2unpack(sz, sz0, sz1);
        const int j0 = tb * TILE + h * 64 + 2 * tid;
        float* __restrict__ fj = out + NBATCH + (size_t)(b * NATOMS + j0) * 3;
        atomicAdd(fj + 0, -12.0f * sx0);
        atomicAdd(fj + 1, -12.0f * sy0);
        atomicAdd(fj + 2, -12.0f * sz0);
        atomicAdd(fj + 3, -12.0f * sx1);
        atomicAdd(fj + 4, -12.0f * sy1);
        atomicAdd(fj + 5, -12.0f * sz1);
    }

    // energy: warp shuffles -> shared -> one atomicAdd per block
    #pragma unroll
    for (int o = 16; o > 0; o >>= 1)
        e += __shfl_xor_sync(0xFFFFFFFFu, e, o);
    if (lane == 0) ered[warp] = e;
    __syncthreads();
    if (tid == 0) atomicAdd(out + b, ered[0] + ered[1]);
}

extern "C" void kernel_launch(void* const* d_in, const int* in_sizes, int n_in,
                              void* d_out, int out_size) {
    const float* pos = (const float*)d_in[0];
    float* out = (float*)d_out;
    lj_pre<<<NBATCH, 256>>>(pos, out);
    lj_kernel<<<NBATCH * BPB, THREADS>>>(pos, out);
}

// round 11
// speedup vs baseline: 1.0553x; 1.0553x over previous
#include <cuda_runtime.h>

#define NATOMS  1024
#define NBATCH  32
#define NTILE   8
#define TILE    128
#define TPAIRS  64            // packed j-pairs per tile
#define NPB     36            // tile-pairs per batch: 8 diag + 28 off-diag
#define THREADS 64            // each thread owns TWO i-atoms (tid, tid+64)
// grid = NBATCH * NPB = 1152 blocks of 64 threads

typedef unsigned long long ull;

__device__ __forceinline__ ull f2pack(float lo, float hi) {
    ull r;
    asm("mov.b64 %0, {%1, %2};" : "=l"(r)
        : "r"(__float_as_uint(lo)), "r"(__float_as_uint(hi)));
    return r;
}
__device__ __forceinline__ void f2unpack(ull v, float& lo, float& hi) {
    unsigned a, b;
    asm("mov.b64 {%0, %1}, %2;" : "=r"(a), "=r"(b) : "l"(v));
    lo = __uint_as_float(a);
    hi = __uint_as_float(b);
}
__device__ __forceinline__ ull f2add(ull a, ull b) {
    ull r; asm("add.rn.f32x2 %0, %1, %2;" : "=l"(r) : "l"(a), "l"(b)); return r;
}
__device__ __forceinline__ ull f2mul(ull a, ull b) {
    ull r; asm("mul.rn.f32x2 %0, %1, %2;" : "=l"(r) : "l"(a), "l"(b)); return r;
}
__device__ __forceinline__ ull f2fma(ull a, ull b, ull c) {
    ull r; asm("fma.rn.f32x2 %0, %1, %2, %3;" : "=l"(r) : "l"(a), "l"(b), "l"(c)); return r;
}

// Pre-pass: 4 blocks per batch. Each block loads the whole batch (4 atoms/thread),
// reduces the mean, computes the full oscillator energy from held registers,
// and initializes forces for its 256-atom quarter (thread t -> atom t + 256*q).
// Quarter-0 block writes out[b] (sole writer; main kernel only atomicAdds after).
__global__ __launch_bounds__(256) void lj_pre(const float* __restrict__ pos,
                                              float* __restrict__ out) {
    __shared__ float wr[8 * 3];
    __shared__ float er[8];
    __shared__ float smean[3];

    const int blk = blockIdx.x;
    const int b   = blk >> 2;
    const int q   = blk & 3;
    const int tid = threadIdx.x;
    const int lane = tid & 31, warp = tid >> 5;
    const float* __restrict__ p = pos + (size_t)b * NATOMS * 3;

    // hold 4 atoms per thread: a = tid + 256*k
    float ax[4], ay[4], az[4];
    float mx = 0.0f, my = 0.0f, mz = 0.0f;
    #pragma unroll
    for (int k = 0; k < 4; k++) {
        const int a = tid + 256 * k;
        ax[k] = p[3 * a + 0]; ay[k] = p[3 * a + 1]; az[k] = p[3 * a + 2];
        mx += ax[k]; my += ay[k]; mz += az[k];
    }
    #pragma unroll
    for (int o = 16; o > 0; o >>= 1) {
        mx += __shfl_xor_sync(0xFFFFFFFFu, mx, o);
        my += __shfl_xor_sync(0xFFFFFFFFu, my, o);
        mz += __shfl_xor_sync(0xFFFFFFFFu, mz, o);
    }
    if (lane == 0) { wr[warp * 3] = mx; wr[warp * 3 + 1] = my; wr[warp * 3 + 2] = mz; }
    __syncthreads();
    if (tid == 0) {
        float sx = 0.0f, sy = 0.0f, sz = 0.0f;
        #pragma unroll
        for (int k = 0; k < 8; k++) { sx += wr[k*3]; sy += wr[k*3+1]; sz += wr[k*3+2]; }
        const float inv_n = 1.0f / (float)NATOMS;
        smean[0] = sx * inv_n; smean[1] = sy * inv_n; smean[2] = sz * inv_n;
    }
    __syncthreads();
    const float cmx = smean[0], cmy = smean[1], cmz = smean[2];

    // oscillator energy over ALL held atoms; force init only for quarter q
    float e = 0.0f;
    float* __restrict__ f = out + NBATCH + (size_t)b * NATOMS * 3;
    #pragma unroll
    for (int k = 0; k < 4; k++) {
        float xc = ax[k] - cmx, yc = ay[k] - cmy, zc = az[k] - cmz;
        e += fmaf(xc, xc, fmaf(yc, yc, zc * zc));
        if (k == q) {
            const int a = tid + 256 * k;
            f[3 * a + 0] = -0.25f * xc;
            f[3 * a + 1] = -0.25f * yc;
            f[3 * a + 2] = -0.25f * zc;
        }
    }
    e *= 0.125f;
    #pragma unroll
    for (int o = 16; o > 0; o >>= 1) e += __shfl_xor_sync(0xFFFFFFFFu, e, o);
    if (lane == 0) er[warp] = e;
    __syncthreads();
    if (q == 0 && tid == 0) {
        float es = 0.0f;
        #pragma unroll
        for (int k = 0; k < 8; k++) es += er[k];
        out[b] = es;
    }
}

// LJ core for one packed i vs one packed j-pair. Returns c2; accumulates e/f.
__device__ __forceinline__ ull lj_core(
    ull xi2, ull yi2, ull zi2, ull nx2, ull ny2, ull nz2,
    int m, int m0, int m1, bool self_mask, ull MINUS1,
    ull& dx2o, ull& dy2o, ull& dz2o,
    ull& fx2, ull& fy2, ull& fz2, ull& ae)
{
    ull dx2 = f2add(xi2, nx2);
    ull dy2 = f2add(yi2, ny2);
    ull dz2 = f2add(zi2, nz2);
    ull sq2 = f2mul(dx2, dx2);
    sq2 = f2fma(dy2, dy2, sq2);
    sq2 = f2fma(dz2, dz2, sq2);
    float s0, s1;
    f2unpack(sq2, s0, s1);
    if (self_mask) {                    // self-pair -> rcp underflows to 0
        s0 = (m == m0) ? 3.0e38f : s0;
        s1 = (m == m1) ? 3.0e38f : s1;
    }
    float r0 = __fdividef(1.0f, s0);    // MUFU.RCP
    float r1 = __fdividef(1.0f, s1);
    ull invsq2 = f2pack(r0, r1);
    ull t4    = f2mul(invsq2, invsq2);
    ull inv6  = f2mul(t4, invsq2);
    ull inv12 = f2mul(inv6, inv6);
    ull diff  = f2fma(inv6, MINUS1, inv12);     // inv12 - inv6
    ae = f2add(ae, f2fma(inv6, MINUS1, diff));  // += inv12 - 2*inv6
    ull c2 = f2mul(diff, invsq2);
    fx2 = f2fma(c2, dx2, fx2);
    fy2 = f2fma(c2, dy2, fy2);
    fz2 = f2fma(c2, dz2, fz2);
    dx2o = dx2; dy2o = dy2; dz2o = dz2;
    return c2;
}

__global__ __launch_bounds__(THREADS, 12) void lj_kernel(const float* __restrict__ pos,
                                                         float* __restrict__ out) {
    __shared__ ulonglong2 sxy[TPAIRS];     // packed negated j-tile (-x0,-x1),(-y0,-y1)
    __shared__ ull        szz[TPAIRS];     // (-z0,-z1)
    __shared__ ull        fjx[2 * TPAIRS]; // per-warp j-force accumulators (packed)
    __shared__ ull        fjy[2 * TPAIRS];
    __shared__ ull        fjz[2 * TPAIRS];
    __shared__ float      ered[2];

    const int bi  = blockIdx.x;
    const int b   = bi / NPB;
    int rem = bi - b * NPB;                // tile-pair rank 0..35
    int ta = 0;
    while (rem >= NTILE - ta) { rem -= NTILE - ta; ta++; }
    const int tb = ta + rem;               // ta <= tb
    const bool diag = (ta == tb);

    const int tid  = threadIdx.x;
    const int lane = tid & 31;
    const int warp = tid >> 5;

    const float* __restrict__ p = pos + (size_t)b * NATOMS * 3;

    // two owned i-atoms
    const int i0 = ta * TILE + tid;
    const int i1 = i0 + THREADS;
    const float xa = p[3 * i0 + 0], ya = p[3 * i0 + 1], za = p[3 * i0 + 2];
    const float xb = p[3 * i1 + 0], yb = p[3 * i1 + 1], zb = p[3 * i1 + 2];

    // stage packed, negated j-tile (tile tb): pair m -> atoms (2m, 2m+1)
    {
        const int j0 = tb * TILE + 2 * tid;
        float x0 = p[3 * j0 + 0], y0 = p[3 * j0 + 1], z0 = p[3 * j0 + 2];
        float x1 = p[3 * j0 + 3], y1 = p[3 * j0 + 4], z1 = p[3 * j0 + 5];
        ulonglong2 v;
        v.x = f2pack(-x0, -x1);
        v.y = f2pack(-y0, -y1);
        sxy[tid] = v;
        szz[tid] = f2pack(-z0, -z1);
    }
    // zero per-warp j-force accumulators (2 warps x 64 pairs)
    #pragma unroll
    for (int k = 0; k < 2; k++) {
        fjx[k * THREADS + tid] = 0;
        fjy[k * THREADS + tid] = 0;
        fjz[k * THREADS + tid] = 0;
    }
    __syncthreads();

    const ull xa2 = f2pack(xa, xa), ya2 = f2pack(ya, ya), za2 = f2pack(za, za);
    const ull xb2 = f2pack(xb, xb), yb2 = f2pack(yb, yb), zb2 = f2pack(zb, zb);
    const ull MINUS1 = f2pack(-1.0f, -1.0f);

    ull fxa = 0, fya = 0, fza = 0, aea = 0;
    ull fxb = 0, fyb = 0, fzb = 0, aeb = 0;

    if (diag) {
        // self-tile: full directed loop with self-pair masks; no j-side accumulation
        const int slot = tid & 1;
        const int m0a = (slot == 0) ? (tid >> 1) : -1;
        const int m1a = (slot == 1) ? (tid >> 1) : -1;
        const int m0b = (slot == 0) ? (32 + (tid >> 1)) : -1;
        const int m1b = (slot == 1) ? (32 + (tid >> 1)) : -1;
        ull d0, d1, d2;
        #pragma unroll 2
        for (int m = 0; m < TPAIRS; m++) {
            ulonglong2 q = sxy[m];
            ull nz2 = szz[m];
            lj_core(xa2, ya2, za2, q.x, q.y, nz2, m, m0a, m1a, true, MINUS1,
                    d0, d1, d2, fxa, fya, fza, aea);
            lj_core(xb2, yb2, zb2, q.x, q.y, nz2, m, m0b, m1b, true, MINUS1,
                    d0, d1, d2, fxb, fyb, fzb, aeb);
        }
    } else {
        // cross-tile: each pair once; per-warp shared j-accumulators (NOT volatile —
        // each lane touches each pp exactly once, warps own disjoint regions, so
        // ptxas may freely batch/pipeline the RMW memory ops).
        ull* __restrict__ vfx = fjx + warp * TPAIRS;
        ull* __restrict__ vfy = fjy + warp * TPAIRS;
        ull* __restrict__ vfz = fjz + warp * TPAIRS;
        ull dxa, dya, dza, dxb, dyb, dzb;
        #pragma unroll 2
        for (int m = 0; m < TPAIRS; m++) {
            const int pp = (m + lane) & (TPAIRS - 1);   // lanes on distinct pairs
            ulonglong2 q = sxy[pp];
            ull nz2 = szz[pp];
            ull ca = lj_core(xa2, ya2, za2, q.x, q.y, nz2, 0, -1, -1, false, MINUS1,
                             dxa, dya, dza, fxa, fya, fza, aea);
            ull cb = lj_core(xb2, yb2, zb2, q.x, q.y, nz2, 0, -1, -1, false, MINUS1,
                             dxb, dyb, dzb, fxb, fyb, fzb, aeb);
            // combined j-side RMW: vf += ca*da + cb*db
            vfx[pp] = f2fma(cb, dxb, f2fma(ca, dxa, vfx[pp]));
            vfy[pp] = f2fma(cb, dyb, f2fma(ca, dya, vfy[pp]));
            vfz[pp] = f2fma(cb, dzb, f2fma(ca, dza, vfz[pp]));
        }
    }

    const float ew = diag ? 0.5f : 1.0f;
    float e;
    {
        float l0, h0, l1, h1;
        f2unpack(aea, l0, h0);
        f2unpack(aeb, l1, h1);
        e = ew * (l0 + h0 + l1 + h1);
    }

    // i-side forces (output preloaded with oscillator force by lj_pre)
    {
        float lo, hi;
        float* __restrict__ fA = out + NBATCH + (size_t)(b * NATOMS + i0) * 3;
        f2unpack(fxa, lo, hi); atomicAdd(fA + 0, 12.0f * (lo + hi));
        f2unpack(fya, lo, hi); atomicAdd(fA + 1, 12.0f * (lo + hi));
        f2unpack(fza, lo, hi); atomicAdd(fA + 2, 12.0f * (lo + hi));
        float* __restrict__ fB = out + NBATCH + (size_t)(b * NATOMS + i1) * 3;
        f2unpack(fxb, lo, hi); atomicAdd(fB + 0, 12.0f * (lo + hi));
        f2unpack(fyb, lo, hi); atomicAdd(fB + 1, 12.0f * (lo + hi));
        f2unpack(fzb, lo, hi); atomicAdd(fB + 2, 12.0f * (lo + hi));
    }

    __syncthreads();

    // j-side forces (off-diag only): reduce the 2 warp copies, negate, scale
    if (!diag) {
        ull sx = f2add(fjx[tid], fjx[TPAIRS + tid]);
        ull sy = f2add(fjy[tid], fjy[TPAIRS + tid]);
        ull sz = f2add(fjz[tid], fjz[TPAIRS + tid]);
        float sx0, sx1, sy0, sy1, sz0, sz1;
        f2unpack(sx, sx0, sx1);
        f2unpack(sy, sy0, sy1);
        f2unpack(sz, sz0, sz1);
        const int j0 = tb * TILE + 2 * tid;
        float* __restrict__ fj = out + NBATCH + (size_t)(b * NATOMS + j0) * 3;
        atomicAdd(fj + 0, -12.0f * sx0);
        atomicAdd(fj + 1, -12.0f * sy0);
        atomicAdd(fj + 2, -12.0f * sz0);
        atomicAdd(fj + 3, -12.0f * sx1);
        atomicAdd(fj + 4, -12.0f * sy1);
        atomicAdd(fj + 5, -12.0f * sz1);
    }

    // energy: warp shuffles -> shared -> one atomicAdd per block
    #pragma unroll
    for (int o = 16; o > 0; o >>= 1)
        e += __shfl_xor_sync(0xFFFFFFFFu, e, o);
    if (lane == 0) ered[warp] = e;
    __syncthreads();
    if (tid == 0) atomicAdd(out + b, ered[0] + ered[1]);
}

extern "C" void kernel_launch(void* const* d_in, const int* in_sizes, int n_in,
                              void* d_out, int out_size) {
    const float* pos = (const float*)d_in[0];
    float* out = (float*)d_out;
    lj_pre<<<4 * NBATCH, 256>>>(pos, out);
    lj_kernel<<<NBATCH * NPB, THREADS>>>(pos, out);
}

// round 12
// speedup vs baseline: 1.0781x; 1.0216x over previous
#include <cuda_runtime.h>

#define NATOMS  1024
#define NBATCH  32
#define NTILE   8
#define TILE    128
#define QUADS   32            // quads of 4 j-atoms per tile
#define NPB     36            // tile-pairs per batch: 8 diag + 28 off-diag
#define THREADS 64            // each thread owns TWO i-atoms (tid, tid+64)
// grid = NBATCH * NPB = 1152 blocks of 64 threads

typedef unsigned long long ull;

__device__ __forceinline__ ull f2pack(float lo, float hi) {
    ull r;
    asm("mov.b64 %0, {%1, %2};" : "=l"(r)
        : "r"(__float_as_uint(lo)), "r"(__float_as_uint(hi)));
    return r;
}
__device__ __forceinline__ void f2unpack(ull v, float& lo, float& hi) {
    unsigned a, b;
    asm("mov.b64 {%0, %1}, %2;" : "=r"(a), "=r"(b) : "l"(v));
    lo = __uint_as_float(a);
    hi = __uint_as_float(b);
}
__device__ __forceinline__ ull f2add(ull a, ull b) {
    ull r; asm("add.rn.f32x2 %0, %1, %2;" : "=l"(r) : "l"(a), "l"(b)); return r;
}
__device__ __forceinline__ ull f2mul(ull a, ull b) {
    ull r; asm("mul.rn.f32x2 %0, %1, %2;" : "=l"(r) : "l"(a), "l"(b)); return r;
}
__device__ __forceinline__ ull f2fma(ull a, ull b, ull c) {
    ull r; asm("fma.rn.f32x2 %0, %1, %2, %3;" : "=l"(r) : "l"(a), "l"(b), "l"(c)); return r;
}

// Pre-pass: 4 blocks per batch; mean + oscillator init (quarter-0 writes out[b]).
__global__ __launch_bounds__(256) void lj_pre(const float* __restrict__ pos,
                                              float* __restrict__ out) {
    __shared__ float wr[8 * 3];
    __shared__ float er[8];
    __shared__ float smean[3];

    const int blk = blockIdx.x;
    const int b   = blk >> 2;
    const int q   = blk & 3;
    const int tid = threadIdx.x;
    const int lane = tid & 31, warp = tid >> 5;
    const float* __restrict__ p = pos + (size_t)b * NATOMS * 3;

    float ax[4], ay[4], az[4];
    float mx = 0.0f, my = 0.0f, mz = 0.0f;
    #pragma unroll
    for (int k = 0; k < 4; k++) {
        const int a = tid + 256 * k;
        ax[k] = p[3 * a + 0]; ay[k] = p[3 * a + 1]; az[k] = p[3 * a + 2];
        mx += ax[k]; my += ay[k]; mz += az[k];
    }
    #pragma unroll
    for (int o = 16; o > 0; o >>= 1) {
        mx += __shfl_xor_sync(0xFFFFFFFFu, mx, o);
        my += __shfl_xor_sync(0xFFFFFFFFu, my, o);
        mz += __shfl_xor_sync(0xFFFFFFFFu, mz, o);
    }
    if (lane == 0) { wr[warp * 3] = mx; wr[warp * 3 + 1] = my; wr[warp * 3 + 2] = mz; }
    __syncthreads();
    if (tid == 0) {
        float sx = 0.0f, sy = 0.0f, sz = 0.0f;
        #pragma unroll
        for (int k = 0; k < 8; k++) { sx += wr[k*3]; sy += wr[k*3+1]; sz += wr[k*3+2]; }
        const float inv_n = 1.0f / (float)NATOMS;
        smean[0] = sx * inv_n; smean[1] = sy * inv_n; smean[2] = sz * inv_n;
    }
    __syncthreads();
    const float cmx = smean[0], cmy = smean[1], cmz = smean[2];

    float e = 0.0f;
    float* __restrict__ f = out + NBATCH + (size_t)b * NATOMS * 3;
    #pragma unroll
    for (int k = 0; k < 4; k++) {
        float xc = ax[k] - cmx, yc = ay[k] - cmy, zc = az[k] - cmz;
        e += fmaf(xc, xc, fmaf(yc, yc, zc * zc));
        if (k == q) {
            const int a = tid + 256 * k;
            f[3 * a + 0] = -0.25f * xc;
            f[3 * a + 1] = -0.25f * yc;
            f[3 * a + 2] = -0.25f * zc;
        }
    }
    e *= 0.125f;
    #pragma unroll
    for (int o = 16; o > 0; o >>= 1) e += __shfl_xor_sync(0xFFFFFFFFu, e, o);
    if (lane == 0) er[warp] = e;
    __syncthreads();
    if (q == 0 && tid == 0) {
        float es = 0.0f;
        #pragma unroll
        for (int k = 0; k < 8; k++) es += er[k];
        out[b] = es;
    }
}

// LJ core for one packed i vs one packed j-pair. Returns c2; accumulates e/f.
__device__ __forceinline__ ull lj_core(
    ull xi2, ull yi2, ull zi2, ull nx2, ull ny2, ull nz2,
    int m, int m0, int m1, bool self_mask, ull MINUS1,
    ull& dx2o, ull& dy2o, ull& dz2o,
    ull& fx2, ull& fy2, ull& fz2, ull& ae)
{
    ull dx2 = f2add(xi2, nx2);
    ull dy2 = f2add(yi2, ny2);
    ull dz2 = f2add(zi2, nz2);
    ull sq2 = f2mul(dx2, dx2);
    sq2 = f2fma(dy2, dy2, sq2);
    sq2 = f2fma(dz2, dz2, sq2);
    float s0, s1;
    f2unpack(sq2, s0, s1);
    if (self_mask) {                    // self-pair -> rcp underflows to 0
        s0 = (m == m0) ? 3.0e38f : s0;
        s1 = (m == m1) ? 3.0e38f : s1;
    }
    float r0 = __fdividef(1.0f, s0);    // MUFU.RCP
    float r1 = __fdividef(1.0f, s1);
    ull invsq2 = f2pack(r0, r1);
    ull t4    = f2mul(invsq2, invsq2);
    ull inv6  = f2mul(t4, invsq2);
    ull inv12 = f2mul(inv6, inv6);
    ull diff  = f2fma(inv6, MINUS1, inv12);     // inv12 - inv6
    ae = f2add(ae, f2fma(inv6, MINUS1, diff));  // += inv12 - 2*inv6
    ull c2 = f2mul(diff, invsq2);
    fx2 = f2fma(c2, dx2, fx2);
    fy2 = f2fma(c2, dy2, fy2);
    fz2 = f2fma(c2, dz2, fz2);
    dx2o = dx2; dy2o = dy2; dz2o = dz2;
    return c2;
}

__global__ __launch_bounds__(THREADS, 10) void lj_kernel(const float* __restrict__ pos,
                                                         float* __restrict__ out) {
    // j-tile in quads: quad q holds atoms 4q..4q+3 (negated)
    __shared__ ulonglong2 sxq[QUADS];      // {x01, x23}
    __shared__ ulonglong2 syq[QUADS];      // {y01, y23}
    __shared__ ulonglong2 szq[QUADS];      // {z01, z23}
    __shared__ ulonglong2 gx[2][QUADS];    // per-warp j-force accumulators
    __shared__ ulonglong2 gy[2][QUADS];
    __shared__ ulonglong2 gz[2][QUADS];
    __shared__ float      ered[2];

    const int bi  = blockIdx.x;
    const int b   = bi / NPB;
    int rem = bi - b * NPB;                // tile-pair rank 0..35
    int ta = 0;
    while (rem >= NTILE - ta) { rem -= NTILE - ta; ta++; }
    const int tb = ta + rem;               // ta <= tb
    const bool diag = (ta == tb);

    const int tid  = threadIdx.x;
    const int lane = tid & 31;
    const int warp = tid >> 5;

    const float* __restrict__ p = pos + (size_t)b * NATOMS * 3;

    // two owned i-atoms
    const int i0 = ta * TILE + tid;
    const int i1 = i0 + THREADS;
    const float xa = p[3 * i0 + 0], ya = p[3 * i0 + 1], za = p[3 * i0 + 2];
    const float xb = p[3 * i1 + 0], yb = p[3 * i1 + 1], zb = p[3 * i1 + 2];

    // stage quads (threads 0..31)
    if (tid < QUADS) {
        const int j0 = tb * TILE + 4 * tid;
        float v0x = p[3*j0+0], v0y = p[3*j0+1],  v0z = p[3*j0+2];
        float v1x = p[3*j0+3], v1y = p[3*j0+4],  v1z = p[3*j0+5];
        float v2x = p[3*j0+6], v2y = p[3*j0+7],  v2z = p[3*j0+8];
        float v3x = p[3*j0+9], v3y = p[3*j0+10], v3z = p[3*j0+11];
        ulonglong2 X, Y, Z;
        X.x = f2pack(-v0x, -v1x); X.y = f2pack(-v2x, -v3x);
        Y.x = f2pack(-v0y, -v1y); Y.y = f2pack(-v2y, -v3y);
        Z.x = f2pack(-v0z, -v1z); Z.y = f2pack(-v2z, -v3z);
        sxq[tid] = X; syq[tid] = Y; szq[tid] = Z;
    }
    // zero accumulators (384 ull total, 64 threads x 6)
    {
        ull* g = (ull*)gx;  // gx, gy, gz are contiguous? not guaranteed — zero each
        #pragma unroll
        for (int k = 0; k < 2; k++) {
            ((ull*)gx)[k * 64 + tid] = 0;
            ((ull*)gy)[k * 64 + tid] = 0;
            ((ull*)gz)[k * 64 + tid] = 0;
        }
        (void)g;
    }
    __syncthreads();

    const ull xa2 = f2pack(xa, xa), ya2 = f2pack(ya, ya), za2 = f2pack(za, za);
    const ull xb2 = f2pack(xb, xb), yb2 = f2pack(yb, yb), zb2 = f2pack(zb, zb);
    const ull MINUS1 = f2pack(-1.0f, -1.0f);

    ull fxa = 0, fya = 0, fza = 0, aea = 0;
    ull fxb = 0, fyb = 0, fzb = 0, aeb = 0;

    if (diag) {
        // self-tile: broadcast over quads; self-masks per sub-pair/slot.
        // atom index of a in tile = tid = 4*qa + 2*sub + slot; b = tid + 64.
        const int qa   = tid >> 2;
        const int qb   = 16 + qa;
        const int sub  = (tid >> 1) & 1;
        const int slot = tid & 1;
        const int a00 = (sub == 0 && slot == 0) ? qa : -1;  // core(a,sub0) elem lo
        const int a01 = (sub == 0 && slot == 1) ? qa : -1;
        const int a10 = (sub == 1 && slot == 0) ? qa : -1;  // core(a,sub1)
        const int a11 = (sub == 1 && slot == 1) ? qa : -1;
        const int b00 = (sub == 0 && slot == 0) ? qb : -1;
        const int b01 = (sub == 0 && slot == 1) ? qb : -1;
        const int b10 = (sub == 1 && slot == 0) ? qb : -1;
        const int b11 = (sub == 1 && slot == 1) ? qb : -1;
        ull d0, d1, d2;
        #pragma unroll 2
        for (int t = 0; t < QUADS; t++) {
            ulonglong2 X = sxq[t], Y = syq[t], Z = szq[t];
            lj_core(xa2, ya2, za2, X.x, Y.x, Z.x, t, a00, a01, true, MINUS1,
                    d0, d1, d2, fxa, fya, fza, aea);
            lj_core(xa2, ya2, za2, X.y, Y.y, Z.y, t, a10, a11, true, MINUS1,
                    d0, d1, d2, fxa, fya, fza, aea);
            lj_core(xb2, yb2, zb2, X.x, Y.x, Z.x, t, b00, b01, true, MINUS1,
                    d0, d1, d2, fxb, fyb, fzb, aeb);
            lj_core(xb2, yb2, zb2, X.y, Y.y, Z.y, t, b10, b11, true, MINUS1,
                    d0, d1, d2, fxb, fyb, fzb, aeb);
        }
    } else {
        // cross-tile: lane rotation over quads; 128-bit j-RMW per component.
        ulonglong2* __restrict__ GX = gx[warp];
        ulonglong2* __restrict__ GY = gy[warp];
        ulonglong2* __restrict__ GZ = gz[warp];
        ull dax0, day0, daz0, dbx0, dby0, dbz0;
        ull dax1, day1, daz1, dbx1, dby1, dbz1;
        #pragma unroll 2
        for (int t = 0; t < QUADS; t++) {
            const int q = (t + lane) & (QUADS - 1);   // lanes on distinct quads
            ulonglong2 X = sxq[q], Y = syq[q], Z = szq[q];
            ull ca0 = lj_core(xa2, ya2, za2, X.x, Y.x, Z.x, 0, -1, -1, false, MINUS1,
                              dax0, day0, daz0, fxa, fya, fza, aea);
            ull cb0 = lj_core(xb2, yb2, zb2, X.x, Y.x, Z.x, 0, -1, -1, false, MINUS1,
                              dbx0, dby0, dbz0, fxb, fyb, fzb, aeb);
            ull ca1 = lj_core(xa2, ya2, za2, X.y, Y.y, Z.y, 0, -1, -1, false, MINUS1,
                              dax1, day1, daz1, fxa, fya, fza, aea);
            ull cb1 = lj_core(xb2, yb2, zb2, X.y, Y.y, Z.y, 0, -1, -1, false, MINUS1,
                              dbx1, dby1, dbz1, fxb, fyb, fzb, aeb);
            ulonglong2 vx = GX[q];
            vx.x = f2fma(cb0, dbx0, f2fma(ca0, dax0, vx.x));
            vx.y = f2fma(cb1, dbx1, f2fma(ca1, dax1, vx.y));
            GX[q] = vx;
            ulonglong2 vy = GY[q];
            vy.x = f2fma(cb0, dby0, f2fma(ca0, day0, vy.x));
            vy.y = f2fma(cb1, dby1, f2fma(ca1, day1, vy.y));
            GY[q] = vy;
            ulonglong2 vz = GZ[q];
            vz.x = f2fma(cb0, dbz0, f2fma(ca0, daz0, vz.x));
            vz.y = f2fma(cb1, dbz1, f2fma(ca1, daz1, vz.y));
            GZ[q] = vz;
        }
    }

    const float ew = diag ? 0.5f : 1.0f;
    float e;
    {
        float l0, h0, l1, h1;
        f2unpack(aea, l0, h0);
        f2unpack(aeb, l1, h1);
        e = ew * (l0 + h0 + l1 + h1);
    }

    // i-side forces (output preloaded with oscillator force by lj_pre)
    {
        float lo, hi;
        float* __restrict__ fA = out + NBATCH + (size_t)(b * NATOMS + i0) * 3;
        f2unpack(fxa, lo, hi); atomicAdd(fA + 0, 12.0f * (lo + hi));
        f2unpack(fya, lo, hi); atomicAdd(fA + 1, 12.0f * (lo + hi));
        f2unpack(fza, lo, hi); atomicAdd(fA + 2, 12.0f * (lo + hi));
        float* __restrict__ fB = out + NBATCH + (size_t)(b * NATOMS + i1) * 3;
        f2unpack(fxb, lo, hi); atomicAdd(fB + 0, 12.0f * (lo + hi));
        f2unpack(fyb, lo, hi); atomicAdd(fB + 1, 12.0f * (lo + hi));
        f2unpack(fzb, lo, hi); atomicAdd(fB + 2, 12.0f * (lo + hi));
    }

    __syncthreads();

    // j-side forces (off-diag only): reduce 2 warp copies per quad, negate, scale
    if (!diag && tid < QUADS) {
        ulonglong2 v0 = gx[0][tid], v1 = gx[1][tid];
        ull sx01 = f2add(v0.x, v1.x), sx23 = f2add(v0.y, v1.y);
        v0 = gy[0][tid]; v1 = gy[1][tid];
        ull sy01 = f2add(v0.x, v1.x), sy23 = f2add(v0.y, v1.y);
        v0 = gz[0][tid]; v1 = gz[1][tid];
        ull sz01 = f2add(v0.x, v1.x), sz23 = f2add(v0.y, v1.y);
        float x0, x1, x2, x3, y0, y1, y2, y3, z0, z1, z2, z3;
        f2unpack(sx01, x0, x1); f2unpack(sx23, x2, x3);
        f2unpack(sy01, y0, y1); f2unpack(sy23, y2, y3);
        f2unpack(sz01, z0, z1); f2unpack(sz23, z2, z3);
        const int j0 = tb * TILE + 4 * tid;
        float* __restrict__ fj = out + NBATCH + (size_t)(b * NATOMS + j0) * 3;
        atomicAdd(fj + 0,  -12.0f * x0);
        atomicAdd(fj + 1,  -12.0f * y0);
        atomicAdd(fj + 2,  -12.0f * z0);
        atomicAdd(fj + 3,  -12.0f * x1);
        atomicAdd(fj + 4,  -12.0f * y1);
        atomicAdd(fj + 5,  -12.0f * z1);
        atomicAdd(fj + 6,  -12.0f * x2);
        atomicAdd(fj + 7,  -12.0f * y2);
        atomicAdd(fj + 8,  -12.0f * z2);
        atomicAdd(fj + 9,  -12.0f * x3);
        atomicAdd(fj + 10, -12.0f * y3);
        atomicAdd(fj + 11, -12.0f * z3);
    }

    // energy: warp shuffles -> shared -> one atomicAdd per block
    #pragma unroll
    for (int o = 16; o > 0; o >>= 1)
        e += __shfl_xor_sync(0xFFFFFFFFu, e, o);
    if (lane == 0) ered[warp] = e;
    __syncthreads();
    if (tid == 0) atomicAdd(out + b, ered[0] + ered[1]);
}

extern "C" void kernel_launch(void* const* d_in, const int* in_sizes, int n_in,
                              void* d_out, int out_size) {
    const float* pos = (const float*)d_in[0];
    float* out = (float*)d_out;
    lj_pre<<<4 * NBATCH, 256>>>(pos, out);
    lj_kernel<<<NBATCH * NPB, THREADS>>>(pos, out);
}